// round 10
// baseline (speedup 1.0000x reference)
#include <cuda_runtime.h>
#include <cuda_bf16.h>
#include <cstdint>

#define N_NODES 100000
#define N_EDGES 1600000
#define D 128
#define D4 (D / 4)
#define CAP 64
#define XSTR 68   // smem row stride in 32-bit words (64 data + 4 pad)

// ---------------- scratch (static __device__, no allocation) ---------------
__device__ float g_h[(size_t)N_NODES * D];              // 51.2 MB  h = x@W
__device__ int   g_counts[N_NODES];                     // per-row cursors
__device__ int2  g_edata[(size_t)N_NODES * CAP];        // {col, val_bits} buckets
__device__ uint32_t g_Whi[D * D / 2];                   // Wt[n][k] bf16 pairs (hi)
__device__ uint32_t g_Wlo[D * D / 2];                   // Wt[n][k] bf16 pairs (lo)

// ---------------------------------------------------------------------------
__device__ __forceinline__ uint32_t pack_bf16(float a, float b) {
    __nv_bfloat162 t = __floats2bfloat162_rn(a, b);
    return *reinterpret_cast<uint32_t*>(&t);
}

__device__ __forceinline__ uint32_t smem_u32(const void* p) {
    uint32_t a;
    asm("{ .reg .u64 t; cvta.to.shared.u64 t, %1; cvt.u32.u64 %0, t; }" : "=r"(a) : "l"(p));
    return a;
}

__device__ __forceinline__ void ldsm_x4(uint32_t addr, uint32_t& r0, uint32_t& r1,
                                        uint32_t& r2, uint32_t& r3) {
    asm volatile("ldmatrix.sync.aligned.m8n8.x4.shared.b16 {%0,%1,%2,%3}, [%4];"
                 : "=r"(r0), "=r"(r1), "=r"(r2), "=r"(r3) : "r"(addr));
}

__device__ __forceinline__ void mma16816(float* d, const uint32_t* a,
                                         uint32_t b0, uint32_t b1) {
    asm volatile(
        "mma.sync.aligned.m16n8k16.row.col.f32.bf16.bf16.f32 "
        "{%0,%1,%2,%3}, {%4,%5,%6,%7}, {%8,%9}, {%0,%1,%2,%3};"
        : "+f"(d[0]), "+f"(d[1]), "+f"(d[2]), "+f"(d[3])
        : "r"(a[0]), "r"(a[1]), "r"(a[2]), "r"(a[3]), "r"(b0), "r"(b1));
}

// ---------------------------------------------------------------------------
// W split precompute.
// ---------------------------------------------------------------------------
__global__ void gin_wsplit_kernel(const float* __restrict__ W) {
    int idx = blockIdx.x * blockDim.x + threadIdx.x;
    if (idx >= D * D / 2) return;
    int n = idx >> 6, kw = idx & 63;
    float v0 = W[(2 * kw) * D + n];
    float v1 = W[(2 * kw + 1) * D + n];
    uint32_t hi = pack_bf16(v0, v1);
    float h0 = __uint_as_float(hi << 16);
    float h1 = __uint_as_float(hi & 0xFFFF0000u);
    g_Whi[idx] = hi;
    g_Wlo[idx] = pack_bf16(v0 - h0, v1 - h1);
}

// ---------------------------------------------------------------------------
// HMMA GEMM: 512 threads / 16 warps; warp tile 32x32 (8 accumulators).
// ---------------------------------------------------------------------------
__global__ void __launch_bounds__(512, 1) gin_gemm_mma_kernel(const float* __restrict__ x) {
    extern __shared__ uint32_t smem[];
    uint32_t* Xhi = smem;                   // [128][XSTR]
    uint32_t* Xlo = Xhi + 128 * XSTR;
    uint32_t* Bhi = Xlo + 128 * XSTR;       // Wt[n][k]
    uint32_t* Blo = Bhi + 128 * XSTR;

    const int tid = threadIdx.x;
    const int wid = tid >> 5;
    const int lane = tid & 31;
    const int rowBase = blockIdx.x * 128;

    // Stage pre-split W (8192 words each).
#pragma unroll
    for (int i = tid; i < D * D / 2; i += 512) {
        int r = i >> 6, w = i & 63;
        Bhi[r * XSTR + w] = g_Whi[i];
        Blo[r * XSTR + w] = g_Wlo[i];
    }

    // Convert x tile f32 -> bf16 hi/lo pairs.
    {
        const float4* x4 = reinterpret_cast<const float4*>(x);
#pragma unroll
        for (int p = 0; p < 8; p++) {
            int flat = p * 2048 + tid * 4;
            int r = flat >> 7, k = flat & 127;
            int rg = rowBase + r;
            float4 v = make_float4(0.f, 0.f, 0.f, 0.f);
            if (rg < N_NODES) v = x4[(size_t)rg * D4 + (k >> 2)];
            uint32_t hi01 = pack_bf16(v.x, v.y);
            uint32_t hi23 = pack_bf16(v.z, v.w);
            float h0 = __uint_as_float(hi01 << 16);
            float h1 = __uint_as_float(hi01 & 0xFFFF0000u);
            float h2 = __uint_as_float(hi23 << 16);
            float h3 = __uint_as_float(hi23 & 0xFFFF0000u);
            int base = r * XSTR + (k >> 1);
            Xhi[base]     = hi01;
            Xhi[base + 1] = hi23;
            Xlo[base]     = pack_bf16(v.x - h0, v.y - h1);
            Xlo[base + 1] = pack_bf16(v.z - h2, v.w - h3);
        }
    }
    __syncthreads();

    const int rw = wid & 3;           // M group: rows rw*32..+31
    const int cw = wid >> 2;          // N group: cols cw*32..+31

    float acc[8][4];
#pragma unroll
    for (int t = 0; t < 8; t++)
#pragma unroll
        for (int i = 0; i < 4; i++) acc[t][i] = 0.f;

    const uint32_t laneRow = ((lane >> 3) & 1) * 8 + (lane & 7);
    const uint32_t laneCol = (lane >> 4) * 4;     // 0 or 4 words (16B)

    const uint32_t XhiA = smem_u32(Xhi);
    const uint32_t XloA = smem_u32(Xlo);
    const uint32_t BhiA = smem_u32(Bhi);
    const uint32_t BloA = smem_u32(Blo);

    uint32_t aOff[2], bOff[2];
#pragma unroll
    for (int mt = 0; mt < 2; mt++)
        aOff[mt] = ((rw * 32 + mt * 16 + laneRow) * XSTR + laneCol) * 4;
#pragma unroll
    for (int q = 0; q < 2; q++)
        bOff[q] = ((cw * 32 + q * 16 + laneRow) * XSTR + laneCol) * 4;

#pragma unroll
    for (int chain = 0; chain < 3; chain++) {
        const uint32_t Ab = (chain == 2) ? XloA : XhiA;
        const uint32_t Bb = (chain == 1) ? BloA : BhiA;
#pragma unroll
        for (int ks = 0; ks < 8; ks++) {
            const uint32_t koff = ks * 32;   // 8 words = k16 step
            uint32_t a0[4], a1[4];
            ldsm_x4(Ab + aOff[0] + koff, a0[0], a0[1], a0[2], a0[3]);
            ldsm_x4(Ab + aOff[1] + koff, a1[0], a1[1], a1[2], a1[3]);
#pragma unroll
            for (int q = 0; q < 2; q++) {
                uint32_t r0, r1, r2, r3;   // r0/r2 = b0/b1 tile 2q; r1/r3 = tile 2q+1
                ldsm_x4(Bb + bOff[q] + koff, r0, r1, r2, r3);
                mma16816(acc[2 * q],         a0, r0, r2);
                mma16816(acc[2 * q + 1],     a0, r1, r3);
                mma16816(acc[4 + 2 * q],     a1, r0, r2);
                mma16816(acc[4 + 2 * q + 1], a1, r1, r3);
            }
        }
    }

    // Epilogue: acc[mt*4+nt] covers rows {r0, r0+8}, col pair c0 + nt*8.
    {
        float2* h2 = reinterpret_cast<float2*>(g_h);
        const int c0 = cw * 32 + 2 * (lane & 3);
#pragma unroll
        for (int mt = 0; mt < 2; mt++) {
            int r0 = rowBase + rw * 32 + mt * 16 + (lane >> 2);
#pragma unroll
            for (int nt = 0; nt < 4; nt++) {
                int cw2 = (c0 + nt * 8) >> 1;
                if (r0 < N_NODES)
                    h2[(size_t)r0 * 64 + cw2] = make_float2(acc[mt * 4 + nt][0], acc[mt * 4 + nt][1]);
                if (r0 + 8 < N_NODES)
                    h2[(size_t)(r0 + 8) * 64 + cw2] = make_float2(acc[mt * 4 + nt][2], acc[mt * 4 + nt][3]);
            }
        }
    }
}

// ---------------------------------------------------------------------------
// Bucket build: zero cursors + one-pass scatter (MLP-4).
// ---------------------------------------------------------------------------
__global__ void gin_zero_kernel() {
    int i = blockIdx.x * blockDim.x + threadIdx.x;
    if (i < N_NODES) g_counts[i] = 0;
}

__global__ void gin_build_kernel(const float* __restrict__ vals,
                                 const int* __restrict__ row,
                                 const int* __restrict__ col) {
    int t = blockIdx.x * blockDim.x + threadIdx.x;
    if (t >= N_EDGES / 4) return;
    int4   r4 = reinterpret_cast<const int4*>(row)[t];
    int4   c4 = reinterpret_cast<const int4*>(col)[t];
    float4 v4 = reinterpret_cast<const float4*>(vals)[t];

    int p;
    p = atomicAdd(&g_counts[r4.x], 1);
    if (p < CAP) g_edata[(size_t)r4.x * CAP + p] = make_int2(c4.x, __float_as_int(v4.x));
    p = atomicAdd(&g_counts[r4.y], 1);
    if (p < CAP) g_edata[(size_t)r4.y * CAP + p] = make_int2(c4.y, __float_as_int(v4.y));
    p = atomicAdd(&g_counts[r4.z], 1);
    if (p < CAP) g_edata[(size_t)r4.z * CAP + p] = make_int2(c4.z, __float_as_int(v4.z));
    p = atomicAdd(&g_counts[r4.w], 1);
    if (p < CAP) g_edata[(size_t)r4.w * CAP + p] = make_int2(c4.w, __float_as_int(v4.w));
}

// ---------------------------------------------------------------------------
// Fused aggregate: one warp per node, 8/4/2/1 gather cascade (MLP-8).
// ---------------------------------------------------------------------------
template <int NSTEP>
__device__ __forceinline__ void agg_step(const int2* __restrict__ ebase, int j,
                                         const float4* __restrict__ h4, int lane,
                                         float4& acc) {
    int2 ed[NSTEP];
    float4 hv[NSTEP];
#pragma unroll
    for (int i = 0; i < NSTEP; i++) ed[i] = __ldg(&ebase[j + i]);
#pragma unroll
    for (int i = 0; i < NSTEP; i++) hv[i] = h4[(size_t)ed[i].x * D4 + lane];
#pragma unroll
    for (int i = 0; i < NSTEP; i++) {
        float v = __int_as_float(ed[i].y);
        acc.x += v * hv[i].x; acc.y += v * hv[i].y;
        acc.z += v * hv[i].z; acc.w += v * hv[i].w;
    }
}

__global__ void gin_aggregate_kernel(const float* __restrict__ bias,
                                     const float* __restrict__ eps,
                                     float* __restrict__ out) {
    const int warp = (blockIdx.x * blockDim.x + threadIdx.x) >> 5;
    const int lane = threadIdx.x & 31;
    if (warp >= N_NODES) return;

    const float4* h4 = reinterpret_cast<const float4*>(g_h);
    const float e1 = 1.0f + __ldg(eps);
    const float4 b = reinterpret_cast<const float4*>(bias)[lane];

    float4 self = h4[(size_t)warp * D4 + lane];
    float4 acc;
    acc.x = e1 * self.x + b.x;
    acc.y = e1 * self.y + b.y;
    acc.z = e1 * self.z + b.z;
    acc.w = e1 * self.w + b.w;

    int deg = __ldg(&g_counts[warp]);
    if (deg > CAP) deg = CAP;
    const int2* ebase = g_edata + (size_t)warp * CAP;

    int j = 0;
    for (; j + 8 <= deg; j += 8) agg_step<8>(ebase, j, h4, lane, acc);
    if (j + 4 <= deg) { agg_step<4>(ebase, j, h4, lane, acc); j += 4; }
    if (j + 2 <= deg) { agg_step<2>(ebase, j, h4, lane, acc); j += 2; }
    if (j < deg)      { agg_step<1>(ebase, j, h4, lane, acc); }

    acc.x = fmaxf(acc.x, 0.f);
    acc.y = fmaxf(acc.y, 0.f);
    acc.z = fmaxf(acc.z, 0.f);
    acc.w = fmaxf(acc.w, 0.f);
    reinterpret_cast<float4*>(out)[(size_t)warp * D4 + lane] = acc;
}

// ---------------------------------------------------------------------------
extern "C" void kernel_launch(void* const* d_in, const int* in_sizes, int n_in,
                              void* d_out, int out_size) {
    const float* x    = (const float*)d_in[0];
    const float* W    = (const float*)d_in[1];
    const float* bias = (const float*)d_in[2];
    const float* eps  = (const float*)d_in[3];
    const float* vals = (const float*)d_in[4];
    const int*   row  = (const int*)d_in[5];
    const int*   col  = (const int*)d_in[6];
    float* out = (float*)d_out;

    const int smemBytes = 4 * 128 * XSTR * sizeof(uint32_t);   // 139264 B
    cudaFuncSetAttribute(gin_gemm_mma_kernel,
                         cudaFuncAttributeMaxDynamicSharedMemorySize, smemBytes);

    static cudaStream_t s2 = nullptr;
    static cudaEvent_t evFork = nullptr, evJoin = nullptr;
    if (s2 == nullptr) {
        cudaStreamCreateWithFlags(&s2, cudaStreamNonBlocking);
        cudaEventCreateWithFlags(&evFork, cudaEventDisableTiming);
        cudaEventCreateWithFlags(&evJoin, cudaEventDisableTiming);
    }

    // Fork: side stream runs the edge-bucket chain.
    cudaEventRecord(evFork, 0);
    cudaStreamWaitEvent(s2, evFork, 0);

    // side stream: zero cursors -> bucket build
    gin_zero_kernel<<<(N_NODES + 255) / 256, 256, 0, s2>>>();
    gin_build_kernel<<<(N_EDGES / 4 + 255) / 256, 256, 0, s2>>>(vals, row, col);

    // main stream: W split -> HMMA GEMM
    gin_wsplit_kernel<<<(D * D / 2 + 255) / 256, 256>>>(W);
    gin_gemm_mma_kernel<<<(N_NODES + 127) / 128, 512, smemBytes>>>(x);

    // Join.
    cudaEventRecord(evJoin, s2);
    cudaStreamWaitEvent(0, evJoin, 0);

    const long long aggThreads = (long long)N_NODES * 32;
    gin_aggregate_kernel<<<(unsigned)((aggThreads + 255) / 256), 256>>>(bias, eps, out);
}

// round 11
// speedup vs baseline: 1.1021x; 1.1021x over previous
#include <cuda_runtime.h>
#include <cuda_bf16.h>
#include <cuda_fp16.h>
#include <cstdint>

#define N_NODES 100000
#define N_EDGES 1600000
#define D 128
#define D4 (D / 4)
#define CAP 64
#define XSTR 68   // smem row stride in 32-bit words (64 data + 4 pad)

// ---------------- scratch (static __device__, no allocation) ---------------
__device__ float   g_h[(size_t)N_NODES * D];            // 51.2 MB  h = x@W (f32)
__device__ __half2 g_h16[(size_t)N_NODES * 64];         // 25.6 MB  h in fp16 (gather copy)
__device__ int     g_counts[N_NODES];                   // per-row cursors
__device__ int2    g_edata[(size_t)N_NODES * CAP];      // {col, val_bits} buckets
__device__ uint32_t g_Whi[D * D / 2];                   // Wt[n][k] bf16 pairs (hi)
__device__ uint32_t g_Wlo[D * D / 2];                   // Wt[n][k] bf16 pairs (lo)

// ---------------------------------------------------------------------------
__device__ __forceinline__ uint32_t pack_bf16(float a, float b) {
    __nv_bfloat162 t = __floats2bfloat162_rn(a, b);
    return *reinterpret_cast<uint32_t*>(&t);
}

__device__ __forceinline__ uint32_t smem_u32(const void* p) {
    uint32_t a;
    asm("{ .reg .u64 t; cvta.to.shared.u64 t, %1; cvt.u32.u64 %0, t; }" : "=r"(a) : "l"(p));
    return a;
}

__device__ __forceinline__ void ldsm_x4(uint32_t addr, uint32_t& r0, uint32_t& r1,
                                        uint32_t& r2, uint32_t& r3) {
    asm volatile("ldmatrix.sync.aligned.m8n8.x4.shared.b16 {%0,%1,%2,%3}, [%4];"
                 : "=r"(r0), "=r"(r1), "=r"(r2), "=r"(r3) : "r"(addr));
}

__device__ __forceinline__ void mma16816(float* d, const uint32_t* a,
                                         uint32_t b0, uint32_t b1) {
    asm volatile(
        "mma.sync.aligned.m16n8k16.row.col.f32.bf16.bf16.f32 "
        "{%0,%1,%2,%3}, {%4,%5,%6,%7}, {%8,%9}, {%0,%1,%2,%3};"
        : "+f"(d[0]), "+f"(d[1]), "+f"(d[2]), "+f"(d[3])
        : "r"(a[0]), "r"(a[1]), "r"(a[2]), "r"(a[3]), "r"(b0), "r"(b1));
}

// ---------------------------------------------------------------------------
// W split precompute.
// ---------------------------------------------------------------------------
__global__ void gin_wsplit_kernel(const float* __restrict__ W) {
    int idx = blockIdx.x * blockDim.x + threadIdx.x;
    if (idx >= D * D / 2) return;
    int n = idx >> 6, kw = idx & 63;
    float v0 = W[(2 * kw) * D + n];
    float v1 = W[(2 * kw + 1) * D + n];
    uint32_t hi = pack_bf16(v0, v1);
    float h0 = __uint_as_float(hi << 16);
    float h1 = __uint_as_float(hi & 0xFFFF0000u);
    g_Whi[idx] = hi;
    g_Wlo[idx] = pack_bf16(v0 - h0, v1 - h1);
}

// ---------------------------------------------------------------------------
// HMMA GEMM (R9 256-thread version): h = x@W, bf16 split, ldmatrix loads.
// Epilogue writes f32 h AND fp16 h copy.
// ---------------------------------------------------------------------------
__global__ void __launch_bounds__(256, 1) gin_gemm_mma_kernel(const float* __restrict__ x) {
    extern __shared__ uint32_t smem[];
    uint32_t* Xhi = smem;                   // [128][XSTR]
    uint32_t* Xlo = Xhi + 128 * XSTR;
    uint32_t* Bhi = Xlo + 128 * XSTR;       // Wt[n][k]
    uint32_t* Blo = Bhi + 128 * XSTR;

    const int tid = threadIdx.x;
    const int wid = tid >> 5;
    const int lane = tid & 31;
    const int rowBase = blockIdx.x * 128;

#pragma unroll
    for (int i = tid; i < D * D / 2; i += 256) {
        int r = i >> 6, w = i & 63;
        Bhi[r * XSTR + w] = g_Whi[i];
        Blo[r * XSTR + w] = g_Wlo[i];
    }

    {
        const float4* x4 = reinterpret_cast<const float4*>(x);
#pragma unroll
        for (int p = 0; p < 16; p++) {
            int flat = p * 1024 + tid * 4;
            int r = flat >> 7, k = flat & 127;
            int rg = rowBase + r;
            float4 v = make_float4(0.f, 0.f, 0.f, 0.f);
            if (rg < N_NODES) v = x4[(size_t)rg * D4 + (k >> 2)];
            uint32_t hi01 = pack_bf16(v.x, v.y);
            uint32_t hi23 = pack_bf16(v.z, v.w);
            float h0 = __uint_as_float(hi01 << 16);
            float h1 = __uint_as_float(hi01 & 0xFFFF0000u);
            float h2 = __uint_as_float(hi23 << 16);
            float h3 = __uint_as_float(hi23 & 0xFFFF0000u);
            int base = r * XSTR + (k >> 1);
            Xhi[base]     = hi01;
            Xhi[base + 1] = hi23;
            Xlo[base]     = pack_bf16(v.x - h0, v.y - h1);
            Xlo[base + 1] = pack_bf16(v.z - h2, v.w - h3);
        }
    }
    __syncthreads();

    const int rw = wid & 3;           // M group: rows rw*32..+31
    const int cw = wid >> 2;          // N group: cols cw*64..+63

    float acc[16][4];
#pragma unroll
    for (int t = 0; t < 16; t++)
#pragma unroll
        for (int i = 0; i < 4; i++) acc[t][i] = 0.f;

    const uint32_t laneRow = ((lane >> 3) & 1) * 8 + (lane & 7);
    const uint32_t laneCol = (lane >> 4) * 4;     // 0 or 4 words (16B)

    const uint32_t XhiA = smem_u32(Xhi);
    const uint32_t XloA = smem_u32(Xlo);
    const uint32_t BhiA = smem_u32(Bhi);
    const uint32_t BloA = smem_u32(Blo);

    uint32_t aOff[2], bOff[4];
#pragma unroll
    for (int mt = 0; mt < 2; mt++)
        aOff[mt] = ((rw * 32 + mt * 16 + laneRow) * XSTR + laneCol) * 4;
#pragma unroll
    for (int q = 0; q < 4; q++)
        bOff[q] = ((cw * 64 + q * 16 + laneRow) * XSTR + laneCol) * 4;

#pragma unroll
    for (int chain = 0; chain < 3; chain++) {
        const uint32_t Ab = (chain == 2) ? XloA : XhiA;
        const uint32_t Bb = (chain == 1) ? BloA : BhiA;
#pragma unroll
        for (int ks = 0; ks < 8; ks++) {
            const uint32_t koff = ks * 32;   // 8 words = k16 step
            uint32_t a0[4], a1[4];
            ldsm_x4(Ab + aOff[0] + koff, a0[0], a0[1], a0[2], a0[3]);
            ldsm_x4(Ab + aOff[1] + koff, a1[0], a1[1], a1[2], a1[3]);
#pragma unroll
            for (int q = 0; q < 4; q++) {
                uint32_t r0, r1, r2, r3;
                ldsm_x4(Bb + bOff[q] + koff, r0, r1, r2, r3);
                mma16816(acc[2 * q],         a0, r0, r2);
                mma16816(acc[2 * q + 1],     a0, r1, r3);
                mma16816(acc[8 + 2 * q],     a1, r0, r2);
                mma16816(acc[8 + 2 * q + 1], a1, r1, r3);
            }
        }
    }

    // Epilogue: write f32 h and fp16 copy.
    {
        float2* h2 = reinterpret_cast<float2*>(g_h);
        const int c0 = cw * 64 + 2 * (lane & 3);
#pragma unroll
        for (int mt = 0; mt < 2; mt++) {
            int r0 = rowBase + rw * 32 + mt * 16 + (lane >> 2);
#pragma unroll
            for (int nt = 0; nt < 8; nt++) {
                int cw2 = (c0 + nt * 8) >> 1;
                const float* a = acc[mt * 8 + nt];
                if (r0 < N_NODES) {
                    h2[(size_t)r0 * 64 + cw2] = make_float2(a[0], a[1]);
                    g_h16[(size_t)r0 * 64 + cw2] = __floats2half2_rn(a[0], a[1]);
                }
                if (r0 + 8 < N_NODES) {
                    h2[(size_t)(r0 + 8) * 64 + cw2] = make_float2(a[2], a[3]);
                    g_h16[(size_t)(r0 + 8) * 64 + cw2] = __floats2half2_rn(a[2], a[3]);
                }
            }
        }
    }
}

// ---------------------------------------------------------------------------
// Bucket build: zero cursors + one-pass scatter (MLP-4).
// ---------------------------------------------------------------------------
__global__ void gin_zero_kernel() {
    int i = blockIdx.x * blockDim.x + threadIdx.x;
    if (i < N_NODES) g_counts[i] = 0;
}

__global__ void gin_build_kernel(const float* __restrict__ vals,
                                 const int* __restrict__ row,
                                 const int* __restrict__ col) {
    int t = blockIdx.x * blockDim.x + threadIdx.x;
    if (t >= N_EDGES / 4) return;
    int4   r4 = reinterpret_cast<const int4*>(row)[t];
    int4   c4 = reinterpret_cast<const int4*>(col)[t];
    float4 v4 = reinterpret_cast<const float4*>(vals)[t];

    int p;
    p = atomicAdd(&g_counts[r4.x], 1);
    if (p < CAP) g_edata[(size_t)r4.x * CAP + p] = make_int2(c4.x, __float_as_int(v4.x));
    p = atomicAdd(&g_counts[r4.y], 1);
    if (p < CAP) g_edata[(size_t)r4.y * CAP + p] = make_int2(c4.y, __float_as_int(v4.y));
    p = atomicAdd(&g_counts[r4.z], 1);
    if (p < CAP) g_edata[(size_t)r4.z * CAP + p] = make_int2(c4.z, __float_as_int(v4.z));
    p = atomicAdd(&g_counts[r4.w], 1);
    if (p < CAP) g_edata[(size_t)r4.w * CAP + p] = make_int2(c4.w, __float_as_int(v4.w));
}

// ---------------------------------------------------------------------------
// Fused aggregate: one warp per node; gathers from the fp16 h copy (256B/row).
// Lane l covers cols 4l..4l+3: one uint2 (2x __half2) per gathered row.
// ---------------------------------------------------------------------------
template <int NSTEP>
__device__ __forceinline__ void agg_step(const int2* __restrict__ ebase, int j,
                                         const uint2* __restrict__ h16, int lane,
                                         float4& acc) {
    int2 ed[NSTEP];
    uint2 hv[NSTEP];
#pragma unroll
    for (int i = 0; i < NSTEP; i++) ed[i] = __ldg(&ebase[j + i]);
#pragma unroll
    for (int i = 0; i < NSTEP; i++) hv[i] = __ldg(&h16[(size_t)ed[i].x * 32 + lane]);
#pragma unroll
    for (int i = 0; i < NSTEP; i++) {
        float v = __int_as_float(ed[i].y);
        float2 f01 = __half22float2(*reinterpret_cast<const __half2*>(&hv[i].x));
        float2 f23 = __half22float2(*reinterpret_cast<const __half2*>(&hv[i].y));
        acc.x += v * f01.x; acc.y += v * f01.y;
        acc.z += v * f23.x; acc.w += v * f23.y;
    }
}

__global__ void gin_aggregate_kernel(const float* __restrict__ bias,
                                     const float* __restrict__ eps,
                                     float* __restrict__ out) {
    const int warp = (blockIdx.x * blockDim.x + threadIdx.x) >> 5;
    const int lane = threadIdx.x & 31;
    if (warp >= N_NODES) return;

    const float4* h4 = reinterpret_cast<const float4*>(g_h);
    const uint2* h16 = reinterpret_cast<const uint2*>(g_h16);
    const float e1 = 1.0f + __ldg(eps);
    const float4 b = reinterpret_cast<const float4*>(bias)[lane];

    float4 self = h4[(size_t)warp * D4 + lane];   // f32 self term
    float4 acc;
    acc.x = e1 * self.x + b.x;
    acc.y = e1 * self.y + b.y;
    acc.z = e1 * self.z + b.z;
    acc.w = e1 * self.w + b.w;

    int deg = __ldg(&g_counts[warp]);
    if (deg > CAP) deg = CAP;
    const int2* ebase = g_edata + (size_t)warp * CAP;

    int j = 0;
    for (; j + 8 <= deg; j += 8) agg_step<8>(ebase, j, h16, lane, acc);
    if (j + 4 <= deg) { agg_step<4>(ebase, j, h16, lane, acc); j += 4; }
    if (j + 2 <= deg) { agg_step<2>(ebase, j, h16, lane, acc); j += 2; }
    if (j < deg)      { agg_step<1>(ebase, j, h16, lane, acc); }

    acc.x = fmaxf(acc.x, 0.f);
    acc.y = fmaxf(acc.y, 0.f);
    acc.z = fmaxf(acc.z, 0.f);
    acc.w = fmaxf(acc.w, 0.f);
    reinterpret_cast<float4*>(out)[(size_t)warp * D4 + lane] = acc;
}

// ---------------------------------------------------------------------------
extern "C" void kernel_launch(void* const* d_in, const int* in_sizes, int n_in,
                              void* d_out, int out_size) {
    const float* x    = (const float*)d_in[0];
    const float* W    = (const float*)d_in[1];
    const float* bias = (const float*)d_in[2];
    const float* eps  = (const float*)d_in[3];
    const float* vals = (const float*)d_in[4];
    const int*   row  = (const int*)d_in[5];
    const int*   col  = (const int*)d_in[6];
    float* out = (float*)d_out;

    const int smemBytes = 4 * 128 * XSTR * sizeof(uint32_t);   // 139264 B
    cudaFuncSetAttribute(gin_gemm_mma_kernel,
                         cudaFuncAttributeMaxDynamicSharedMemorySize, smemBytes);

    static cudaStream_t s2 = nullptr;
    static cudaEvent_t evFork = nullptr, evJoin = nullptr;
    if (s2 == nullptr) {
        cudaStreamCreateWithFlags(&s2, cudaStreamNonBlocking);
        cudaEventCreateWithFlags(&evFork, cudaEventDisableTiming);
        cudaEventCreateWithFlags(&evJoin, cudaEventDisableTiming);
    }

    // Fork: side stream runs the edge-bucket chain.
    cudaEventRecord(evFork, 0);
    cudaStreamWaitEvent(s2, evFork, 0);

    // side stream: zero cursors -> bucket build
    gin_zero_kernel<<<(N_NODES + 255) / 256, 256, 0, s2>>>();
    gin_build_kernel<<<(N_EDGES / 4 + 255) / 256, 256, 0, s2>>>(vals, row, col);

    // main stream: W split -> HMMA GEMM (256 threads, R9 config)
    gin_wsplit_kernel<<<(D * D / 2 + 255) / 256, 256>>>(W);
    gin_gemm_mma_kernel<<<(N_NODES + 127) / 128, 256, smemBytes>>>(x);

    // Join.
    cudaEventRecord(evJoin, s2);
    cudaStreamWaitEvent(0, evJoin, 0);

    const long long aggThreads = (long long)N_NODES * 32;
    gin_aggregate_kernel<<<(unsigned)((aggThreads + 255) / 256), 256>>>(bias, eps, out);
}

// round 12
// speedup vs baseline: 1.2619x; 1.1450x over previous
#include <cuda_runtime.h>
#include <cuda_bf16.h>
#include <cuda_fp16.h>
#include <cstdint>

#define N_NODES 100000
#define N_EDGES 1600000
#define D 128
#define D4 (D / 4)
#define CAP 64
#define XSTR 68   // smem row stride in 32-bit words (64 data + 4 pad)

// ---------------- scratch (static __device__, no allocation) ---------------
__device__ __half2 g_h16[(size_t)N_NODES * 64];         // 25.6 MB  h in fp16 (only copy)
__device__ int     g_counts[N_NODES];                   // per-row cursors
__device__ int2    g_edata[(size_t)N_NODES * CAP];      // {col, val_bits} buckets
__device__ uint32_t g_Whi[D * D / 2];                   // Wt[n][k] bf16 pairs (hi)
__device__ uint32_t g_Wlo[D * D / 2];                   // Wt[n][k] bf16 pairs (lo)

// ---------------------------------------------------------------------------
__device__ __forceinline__ uint32_t pack_bf16(float a, float b) {
    __nv_bfloat162 t = __floats2bfloat162_rn(a, b);
    return *reinterpret_cast<uint32_t*>(&t);
}

__device__ __forceinline__ uint32_t smem_u32(const void* p) {
    uint32_t a;
    asm("{ .reg .u64 t; cvta.to.shared.u64 t, %1; cvt.u32.u64 %0, t; }" : "=r"(a) : "l"(p));
    return a;
}

__device__ __forceinline__ void ldsm_x4(uint32_t addr, uint32_t& r0, uint32_t& r1,
                                        uint32_t& r2, uint32_t& r3) {
    asm volatile("ldmatrix.sync.aligned.m8n8.x4.shared.b16 {%0,%1,%2,%3}, [%4];"
                 : "=r"(r0), "=r"(r1), "=r"(r2), "=r"(r3) : "r"(addr));
}

__device__ __forceinline__ void mma16816(float* d, const uint32_t* a,
                                         uint32_t b0, uint32_t b1) {
    asm volatile(
        "mma.sync.aligned.m16n8k16.row.col.f32.bf16.bf16.f32 "
        "{%0,%1,%2,%3}, {%4,%5,%6,%7}, {%8,%9}, {%0,%1,%2,%3};"
        : "+f"(d[0]), "+f"(d[1]), "+f"(d[2]), "+f"(d[3])
        : "r"(a[0]), "r"(a[1]), "r"(a[2]), "r"(a[3]), "r"(b0), "r"(b1));
}

// ---------------------------------------------------------------------------
// W split precompute.
// ---------------------------------------------------------------------------
__global__ void gin_wsplit_kernel(const float* __restrict__ W) {
    int idx = blockIdx.x * blockDim.x + threadIdx.x;
    if (idx >= D * D / 2) return;
    int n = idx >> 6, kw = idx & 63;
    float v0 = W[(2 * kw) * D + n];
    float v1 = W[(2 * kw + 1) * D + n];
    uint32_t hi = pack_bf16(v0, v1);
    float h0 = __uint_as_float(hi << 16);
    float h1 = __uint_as_float(hi & 0xFFFF0000u);
    g_Whi[idx] = hi;
    g_Wlo[idx] = pack_bf16(v0 - h0, v1 - h1);
}

// ---------------------------------------------------------------------------
// HMMA GEMM (R9 config): h = x@W, bf16 split, ldmatrix loads.
// Epilogue writes ONLY the fp16 h copy (25.6 MB).
// ---------------------------------------------------------------------------
__global__ void __launch_bounds__(256, 1) gin_gemm_mma_kernel(const float* __restrict__ x) {
    extern __shared__ uint32_t smem[];
    uint32_t* Xhi = smem;                   // [128][XSTR]
    uint32_t* Xlo = Xhi + 128 * XSTR;
    uint32_t* Bhi = Xlo + 128 * XSTR;       // Wt[n][k]
    uint32_t* Blo = Bhi + 128 * XSTR;

    const int tid = threadIdx.x;
    const int wid = tid >> 5;
    const int lane = tid & 31;
    const int rowBase = blockIdx.x * 128;

#pragma unroll
    for (int i = tid; i < D * D / 2; i += 256) {
        int r = i >> 6, w = i & 63;
        Bhi[r * XSTR + w] = g_Whi[i];
        Blo[r * XSTR + w] = g_Wlo[i];
    }

    {
        const float4* x4 = reinterpret_cast<const float4*>(x);
#pragma unroll
        for (int p = 0; p < 16; p++) {
            int flat = p * 1024 + tid * 4;
            int r = flat >> 7, k = flat & 127;
            int rg = rowBase + r;
            float4 v = make_float4(0.f, 0.f, 0.f, 0.f);
            if (rg < N_NODES) v = x4[(size_t)rg * D4 + (k >> 2)];
            uint32_t hi01 = pack_bf16(v.x, v.y);
            uint32_t hi23 = pack_bf16(v.z, v.w);
            float h0 = __uint_as_float(hi01 << 16);
            float h1 = __uint_as_float(hi01 & 0xFFFF0000u);
            float h2 = __uint_as_float(hi23 << 16);
            float h3 = __uint_as_float(hi23 & 0xFFFF0000u);
            int base = r * XSTR + (k >> 1);
            Xhi[base]     = hi01;
            Xhi[base + 1] = hi23;
            Xlo[base]     = pack_bf16(v.x - h0, v.y - h1);
            Xlo[base + 1] = pack_bf16(v.z - h2, v.w - h3);
        }
    }
    __syncthreads();

    const int rw = wid & 3;           // M group: rows rw*32..+31
    const int cw = wid >> 2;          // N group: cols cw*64..+63

    float acc[16][4];
#pragma unroll
    for (int t = 0; t < 16; t++)
#pragma unroll
        for (int i = 0; i < 4; i++) acc[t][i] = 0.f;

    const uint32_t laneRow = ((lane >> 3) & 1) * 8 + (lane & 7);
    const uint32_t laneCol = (lane >> 4) * 4;     // 0 or 4 words (16B)

    const uint32_t XhiA = smem_u32(Xhi);
    const uint32_t XloA = smem_u32(Xlo);
    const uint32_t BhiA = smem_u32(Bhi);
    const uint32_t BloA = smem_u32(Blo);

    uint32_t aOff[2], bOff[4];
#pragma unroll
    for (int mt = 0; mt < 2; mt++)
        aOff[mt] = ((rw * 32 + mt * 16 + laneRow) * XSTR + laneCol) * 4;
#pragma unroll
    for (int q = 0; q < 4; q++)
        bOff[q] = ((cw * 64 + q * 16 + laneRow) * XSTR + laneCol) * 4;

#pragma unroll
    for (int chain = 0; chain < 3; chain++) {
        const uint32_t Ab = (chain == 2) ? XloA : XhiA;
        const uint32_t Bb = (chain == 1) ? BloA : BhiA;
#pragma unroll
        for (int ks = 0; ks < 8; ks++) {
            const uint32_t koff = ks * 32;   // 8 words = k16 step
            uint32_t a0[4], a1[4];
            ldsm_x4(Ab + aOff[0] + koff, a0[0], a0[1], a0[2], a0[3]);
            ldsm_x4(Ab + aOff[1] + koff, a1[0], a1[1], a1[2], a1[3]);
#pragma unroll
            for (int q = 0; q < 4; q++) {
                uint32_t r0, r1, r2, r3;
                ldsm_x4(Bb + bOff[q] + koff, r0, r1, r2, r3);
                mma16816(acc[2 * q],         a0, r0, r2);
                mma16816(acc[2 * q + 1],     a0, r1, r3);
                mma16816(acc[8 + 2 * q],     a1, r0, r2);
                mma16816(acc[8 + 2 * q + 1], a1, r1, r3);
            }
        }
    }

    // Epilogue: fp16 only.
    {
        const int c0 = cw * 64 + 2 * (lane & 3);
#pragma unroll
        for (int mt = 0; mt < 2; mt++) {
            int r0 = rowBase + rw * 32 + mt * 16 + (lane >> 2);
#pragma unroll
            for (int nt = 0; nt < 8; nt++) {
                int cw2 = (c0 + nt * 8) >> 1;
                const float* a = acc[mt * 8 + nt];
                if (r0 < N_NODES)
                    g_h16[(size_t)r0 * 64 + cw2] = __floats2half2_rn(a[0], a[1]);
                if (r0 + 8 < N_NODES)
                    g_h16[(size_t)(r0 + 8) * 64 + cw2] = __floats2half2_rn(a[2], a[3]);
            }
        }
    }
}

// ---------------------------------------------------------------------------
// Bucket build: zero cursors + one-pass scatter (MLP-4).
// ---------------------------------------------------------------------------
__global__ void gin_zero_kernel() {
    int i = blockIdx.x * blockDim.x + threadIdx.x;
    if (i < N_NODES) g_counts[i] = 0;
}

__global__ void gin_build_kernel(const float* __restrict__ vals,
                                 const int* __restrict__ row,
                                 const int* __restrict__ col) {
    int t = blockIdx.x * blockDim.x + threadIdx.x;
    if (t >= N_EDGES / 4) return;
    int4   r4 = reinterpret_cast<const int4*>(row)[t];
    int4   c4 = reinterpret_cast<const int4*>(col)[t];
    float4 v4 = reinterpret_cast<const float4*>(vals)[t];

    int p;
    p = atomicAdd(&g_counts[r4.x], 1);
    if (p < CAP) g_edata[(size_t)r4.x * CAP + p] = make_int2(c4.x, __float_as_int(v4.x));
    p = atomicAdd(&g_counts[r4.y], 1);
    if (p < CAP) g_edata[(size_t)r4.y * CAP + p] = make_int2(c4.y, __float_as_int(v4.y));
    p = atomicAdd(&g_counts[r4.z], 1);
    if (p < CAP) g_edata[(size_t)r4.z * CAP + p] = make_int2(c4.z, __float_as_int(v4.z));
    p = atomicAdd(&g_counts[r4.w], 1);
    if (p < CAP) g_edata[(size_t)r4.w * CAP + p] = make_int2(c4.w, __float_as_int(v4.w));
}

// ---------------------------------------------------------------------------
// Fused aggregate: one warp per node; self + gathers all from fp16 h.
// Lane l covers cols 4l..4l+3: one uint2 (2x __half2) per row.
// ---------------------------------------------------------------------------
template <int NSTEP>
__device__ __forceinline__ void agg_step(const int2* __restrict__ ebase, int j,
                                         const uint2* __restrict__ h16, int lane,
                                         float4& acc) {
    int2 ed[NSTEP];
    uint2 hv[NSTEP];
#pragma unroll
    for (int i = 0; i < NSTEP; i++) ed[i] = __ldg(&ebase[j + i]);
#pragma unroll
    for (int i = 0; i < NSTEP; i++) hv[i] = __ldg(&h16[(size_t)ed[i].x * 32 + lane]);
#pragma unroll
    for (int i = 0; i < NSTEP; i++) {
        float v = __int_as_float(ed[i].y);
        float2 f01 = __half22float2(*reinterpret_cast<const __half2*>(&hv[i].x));
        float2 f23 = __half22float2(*reinterpret_cast<const __half2*>(&hv[i].y));
        acc.x += v * f01.x; acc.y += v * f01.y;
        acc.z += v * f23.x; acc.w += v * f23.y;
    }
}

__global__ void gin_aggregate_kernel(const float* __restrict__ bias,
                                     const float* __restrict__ eps,
                                     float* __restrict__ out) {
    const int warp = (blockIdx.x * blockDim.x + threadIdx.x) >> 5;
    const int lane = threadIdx.x & 31;
    if (warp >= N_NODES) return;

    const uint2* h16 = reinterpret_cast<const uint2*>(g_h16);
    const float e1 = 1.0f + __ldg(eps);
    const float4 b = reinterpret_cast<const float4*>(bias)[lane];

    uint2 su = __ldg(&h16[(size_t)warp * 32 + lane]);   // fp16 self term
    float2 s01 = __half22float2(*reinterpret_cast<const __half2*>(&su.x));
    float2 s23 = __half22float2(*reinterpret_cast<const __half2*>(&su.y));
    float4 acc;
    acc.x = e1 * s01.x + b.x;
    acc.y = e1 * s01.y + b.y;
    acc.z = e1 * s23.x + b.z;
    acc.w = e1 * s23.y + b.w;

    int deg = __ldg(&g_counts[warp]);
    if (deg > CAP) deg = CAP;
    const int2* ebase = g_edata + (size_t)warp * CAP;

    int j = 0;
    for (; j + 8 <= deg; j += 8) agg_step<8>(ebase, j, h16, lane, acc);
    if (j + 4 <= deg) { agg_step<4>(ebase, j, h16, lane, acc); j += 4; }
    if (j + 2 <= deg) { agg_step<2>(ebase, j, h16, lane, acc); j += 2; }
    if (j < deg)      { agg_step<1>(ebase, j, h16, lane, acc); }

    acc.x = fmaxf(acc.x, 0.f);
    acc.y = fmaxf(acc.y, 0.f);
    acc.z = fmaxf(acc.z, 0.f);
    acc.w = fmaxf(acc.w, 0.f);
    reinterpret_cast<float4*>(out)[(size_t)warp * D4 + lane] = acc;
}

// ---------------------------------------------------------------------------
extern "C" void kernel_launch(void* const* d_in, const int* in_sizes, int n_in,
                              void* d_out, int out_size) {
    const float* x    = (const float*)d_in[0];
    const float* W    = (const float*)d_in[1];
    const float* bias = (const float*)d_in[2];
    const float* eps  = (const float*)d_in[3];
    const float* vals = (const float*)d_in[4];
    const int*   row  = (const int*)d_in[5];
    const int*   col  = (const int*)d_in[6];
    float* out = (float*)d_out;

    const int smemBytes = 4 * 128 * XSTR * sizeof(uint32_t);   // 139264 B
    cudaFuncSetAttribute(gin_gemm_mma_kernel,
                         cudaFuncAttributeMaxDynamicSharedMemorySize, smemBytes);

    static cudaStream_t s2 = nullptr;
    static cudaEvent_t evFork = nullptr, evJoin = nullptr;
    if (s2 == nullptr) {
        cudaStreamCreateWithFlags(&s2, cudaStreamNonBlocking);
        cudaEventCreateWithFlags(&evFork, cudaEventDisableTiming);
        cudaEventCreateWithFlags(&evJoin, cudaEventDisableTiming);
    }

    // Fork: side stream runs the edge-bucket chain.
    cudaEventRecord(evFork, 0);
    cudaStreamWaitEvent(s2, evFork, 0);

    // side stream: zero cursors -> bucket build
    gin_zero_kernel<<<(N_NODES + 255) / 256, 256, 0, s2>>>();
    gin_build_kernel<<<(N_EDGES / 4 + 255) / 256, 256, 0, s2>>>(vals, row, col);

    // main stream: W split -> HMMA GEMM
    gin_wsplit_kernel<<<(D * D / 2 + 255) / 256, 256>>>(W);
    gin_gemm_mma_kernel<<<(N_NODES + 127) / 128, 256, smemBytes>>>(x);

    // Join.
    cudaEventRecord(evJoin, s2);
    cudaStreamWaitEvent(0, evJoin, 0);

    const long long aggThreads = (long long)N_NODES * 32;
    gin_aggregate_kernel<<<(unsigned)((aggThreads + 255) / 256), 256>>>(bias, eps, out);
}

// round 13
// speedup vs baseline: 1.6014x; 1.2691x over previous
#include <cuda_runtime.h>
#include <cuda_fp16.h>
#include <cstdint>

#define N_NODES 100000
#define N_EDGES 1600000
#define D 128
#define D4 (D / 4)
#define CAP 64
#define XSTR 68   // smem row stride in 32-bit words (64 data + 4 pad)

// ---------------- scratch (static __device__, no allocation) ---------------
__device__ __half2 g_h16[(size_t)N_NODES * 64];         // 25.6 MB  h in fp16 (only copy)
__device__ int     g_counts[N_NODES];                   // per-row cursors
__device__ int2    g_edata[(size_t)N_NODES * CAP];      // {col, val_bits} buckets
__device__ uint32_t g_W16[D * D / 2];                   // Wt[n][k] fp16 pairs

// ---------------------------------------------------------------------------
__device__ __forceinline__ uint32_t pack_f16(float a, float b) {
    __half2 t = __floats2half2_rn(a, b);
    return *reinterpret_cast<uint32_t*>(&t);
}

__device__ __forceinline__ uint32_t smem_u32(const void* p) {
    uint32_t a;
    asm("{ .reg .u64 t; cvta.to.shared.u64 t, %1; cvt.u32.u64 %0, t; }" : "=r"(a) : "l"(p));
    return a;
}

__device__ __forceinline__ void ldsm_x4(uint32_t addr, uint32_t& r0, uint32_t& r1,
                                        uint32_t& r2, uint32_t& r3) {
    asm volatile("ldmatrix.sync.aligned.m8n8.x4.shared.b16 {%0,%1,%2,%3}, [%4];"
                 : "=r"(r0), "=r"(r1), "=r"(r2), "=r"(r3) : "r"(addr));
}

__device__ __forceinline__ void mma16816(float* d, const uint32_t* a,
                                         uint32_t b0, uint32_t b1) {
    asm volatile(
        "mma.sync.aligned.m16n8k16.row.col.f32.f16.f16.f32 "
        "{%0,%1,%2,%3}, {%4,%5,%6,%7}, {%8,%9}, {%0,%1,%2,%3};"
        : "+f"(d[0]), "+f"(d[1]), "+f"(d[2]), "+f"(d[3])
        : "r"(a[0]), "r"(a[1]), "r"(a[2]), "r"(a[3]), "r"(b0), "r"(b1));
}

// ---------------------------------------------------------------------------
// W precompute: g_W16[n*64 + kw] = {W[2kw][n], W[2kw+1][n]} as fp16.
// ---------------------------------------------------------------------------
__global__ void gin_wsplit_kernel(const float* __restrict__ W) {
    int idx = blockIdx.x * blockDim.x + threadIdx.x;
    if (idx >= D * D / 2) return;
    int n = idx >> 6, kw = idx & 63;
    g_W16[idx] = pack_f16(W[(2 * kw) * D + n], W[(2 * kw + 1) * D + n]);
}

// ---------------------------------------------------------------------------
// HMMA GEMM: single fp16 chain, 256 threads, 2 CTAs/SM (69.6 KB smem).
// Block tile 128x128; warp tile 32x64 (4 M-groups x 2 N-groups).
// ---------------------------------------------------------------------------
__global__ void __launch_bounds__(256, 2) gin_gemm_mma_kernel(const float* __restrict__ x) {
    extern __shared__ uint32_t smem[];
    uint32_t* Xh = smem;                    // [128][XSTR] fp16 pairs of x
    uint32_t* Bh = Xh + 128 * XSTR;         // [128][XSTR] fp16 pairs of Wt

    const int tid = threadIdx.x;
    const int wid = tid >> 5;
    const int lane = tid & 31;
    const int rowBase = blockIdx.x * 128;

    // Stage W tile.
#pragma unroll
    for (int i = tid; i < D * D / 2; i += 256) {
        Bh[(i >> 6) * XSTR + (i & 63)] = g_W16[i];
    }

    // Convert x tile f32 -> fp16 pairs (coalesced float4 loads).
    {
        const float4* x4 = reinterpret_cast<const float4*>(x);
#pragma unroll
        for (int p = 0; p < 16; p++) {
            int flat = p * 1024 + tid * 4;
            int r = flat >> 7, k = flat & 127;
            int rg = rowBase + r;
            float4 v = make_float4(0.f, 0.f, 0.f, 0.f);
            if (rg < N_NODES) v = x4[(size_t)rg * D4 + (k >> 2)];
            int base = r * XSTR + (k >> 1);
            Xh[base]     = pack_f16(v.x, v.y);
            Xh[base + 1] = pack_f16(v.z, v.w);
        }
    }
    __syncthreads();

    const int rw = wid & 3;           // M group: rows rw*32..+31
    const int cw = wid >> 2;          // N group: cols cw*64..+63

    float acc[16][4];
#pragma unroll
    for (int t = 0; t < 16; t++)
#pragma unroll
        for (int i = 0; i < 4; i++) acc[t][i] = 0.f;

    const uint32_t laneRow = ((lane >> 3) & 1) * 8 + (lane & 7);
    const uint32_t laneCol = (lane >> 4) * 4;     // 0 or 4 words (16B)

    const uint32_t XhA = smem_u32(Xh);
    const uint32_t BhA = smem_u32(Bh);

    uint32_t aOff[2], bOff[4];
#pragma unroll
    for (int mt = 0; mt < 2; mt++)
        aOff[mt] = ((rw * 32 + mt * 16 + laneRow) * XSTR + laneCol) * 4;
#pragma unroll
    for (int q = 0; q < 4; q++)
        bOff[q] = ((cw * 64 + q * 16 + laneRow) * XSTR + laneCol) * 4;

#pragma unroll
    for (int ks = 0; ks < 8; ks++) {
        const uint32_t koff = ks * 32;   // 8 words = k16 step
        uint32_t a0[4], a1[4];
        ldsm_x4(XhA + aOff[0] + koff, a0[0], a0[1], a0[2], a0[3]);
        ldsm_x4(XhA + aOff[1] + koff, a1[0], a1[1], a1[2], a1[3]);
#pragma unroll
        for (int q = 0; q < 4; q++) {
            uint32_t r0, r1, r2, r3;   // r0/r2 = b0/b1 tile 2q; r1/r3 = tile 2q+1
            ldsm_x4(BhA + bOff[q] + koff, r0, r1, r2, r3);
            mma16816(acc[2 * q],         a0, r0, r2);
            mma16816(acc[2 * q + 1],     a0, r1, r3);
            mma16816(acc[8 + 2 * q],     a1, r0, r2);
            mma16816(acc[8 + 2 * q + 1], a1, r1, r3);
        }
    }

    // Epilogue: fp16 h only.
    {
        const int c0 = cw * 64 + 2 * (lane & 3);
#pragma unroll
        for (int mt = 0; mt < 2; mt++) {
            int r0 = rowBase + rw * 32 + mt * 16 + (lane >> 2);
#pragma unroll
            for (int nt = 0; nt < 8; nt++) {
                int cw2 = (c0 + nt * 8) >> 1;
                const float* a = acc[mt * 8 + nt];
                if (r0 < N_NODES)
                    g_h16[(size_t)r0 * 64 + cw2] = __floats2half2_rn(a[0], a[1]);
                if (r0 + 8 < N_NODES)
                    g_h16[(size_t)(r0 + 8) * 64 + cw2] = __floats2half2_rn(a[2], a[3]);
            }
        }
    }
}

// ---------------------------------------------------------------------------
// Bucket build: zero cursors + one-pass scatter (MLP-4).
// ---------------------------------------------------------------------------
__global__ void gin_zero_kernel() {
    int i = blockIdx.x * blockDim.x + threadIdx.x;
    if (i < N_NODES) g_counts[i] = 0;
}

__global__ void gin_build_kernel(const float* __restrict__ vals,
                                 const int* __restrict__ row,
                                 const int* __restrict__ col) {
    int t = blockIdx.x * blockDim.x + threadIdx.x;
    if (t >= N_EDGES / 4) return;
    int4   r4 = reinterpret_cast<const int4*>(row)[t];
    int4   c4 = reinterpret_cast<const int4*>(col)[t];
    float4 v4 = reinterpret_cast<const float4*>(vals)[t];

    int p;
    p = atomicAdd(&g_counts[r4.x], 1);
    if (p < CAP) g_edata[(size_t)r4.x * CAP + p] = make_int2(c4.x, __float_as_int(v4.x));
    p = atomicAdd(&g_counts[r4.y], 1);
    if (p < CAP) g_edata[(size_t)r4.y * CAP + p] = make_int2(c4.y, __float_as_int(v4.y));
    p = atomicAdd(&g_counts[r4.z], 1);
    if (p < CAP) g_edata[(size_t)r4.z * CAP + p] = make_int2(c4.z, __float_as_int(v4.z));
    p = atomicAdd(&g_counts[r4.w], 1);
    if (p < CAP) g_edata[(size_t)r4.w * CAP + p] = make_int2(c4.w, __float_as_int(v4.w));
}

// ---------------------------------------------------------------------------
// Fused aggregate: one warp per node; self + gathers all from fp16 h.
// ---------------------------------------------------------------------------
template <int NSTEP>
__device__ __forceinline__ void agg_step(const int2* __restrict__ ebase, int j,
                                         const uint2* __restrict__ h16, int lane,
                                         float4& acc) {
    int2 ed[NSTEP];
    uint2 hv[NSTEP];
#pragma unroll
    for (int i = 0; i < NSTEP; i++) ed[i] = __ldg(&ebase[j + i]);
#pragma unroll
    for (int i = 0; i < NSTEP; i++) hv[i] = __ldg(&h16[(size_t)ed[i].x * 32 + lane]);
#pragma unroll
    for (int i = 0; i < NSTEP; i++) {
        float v = __int_as_float(ed[i].y);
        float2 f01 = __half22float2(*reinterpret_cast<const __half2*>(&hv[i].x));
        float2 f23 = __half22float2(*reinterpret_cast<const __half2*>(&hv[i].y));
        acc.x += v * f01.x; acc.y += v * f01.y;
        acc.z += v * f23.x; acc.w += v * f23.y;
    }
}

__global__ void gin_aggregate_kernel(const float* __restrict__ bias,
                                     const float* __restrict__ eps,
                                     float* __restrict__ out) {
    const int warp = (blockIdx.x * blockDim.x + threadIdx.x) >> 5;
    const int lane = threadIdx.x & 31;
    if (warp >= N_NODES) return;

    const uint2* h16 = reinterpret_cast<const uint2*>(g_h16);
    const float e1 = 1.0f + __ldg(eps);
    const float4 b = reinterpret_cast<const float4*>(bias)[lane];

    uint2 su = __ldg(&h16[(size_t)warp * 32 + lane]);   // fp16 self term
    float2 s01 = __half22float2(*reinterpret_cast<const __half2*>(&su.x));
    float2 s23 = __half22float2(*reinterpret_cast<const __half2*>(&su.y));
    float4 acc;
    acc.x = e1 * s01.x + b.x;
    acc.y = e1 * s01.y + b.y;
    acc.z = e1 * s23.x + b.z;
    acc.w = e1 * s23.y + b.w;

    int deg = __ldg(&g_counts[warp]);
    if (deg > CAP) deg = CAP;
    const int2* ebase = g_edata + (size_t)warp * CAP;

    int j = 0;
    for (; j + 8 <= deg; j += 8) agg_step<8>(ebase, j, h16, lane, acc);
    if (j + 4 <= deg) { agg_step<4>(ebase, j, h16, lane, acc); j += 4; }
    if (j + 2 <= deg) { agg_step<2>(ebase, j, h16, lane, acc); j += 2; }
    if (j < deg)      { agg_step<1>(ebase, j, h16, lane, acc); }

    acc.x = fmaxf(acc.x, 0.f);
    acc.y = fmaxf(acc.y, 0.f);
    acc.z = fmaxf(acc.z, 0.f);
    acc.w = fmaxf(acc.w, 0.f);
    reinterpret_cast<float4*>(out)[(size_t)warp * D4 + lane] = acc;
}

// ---------------------------------------------------------------------------
extern "C" void kernel_launch(void* const* d_in, const int* in_sizes, int n_in,
                              void* d_out, int out_size) {
    const float* x    = (const float*)d_in[0];
    const float* W    = (const float*)d_in[1];
    const float* bias = (const float*)d_in[2];
    const float* eps  = (const float*)d_in[3];
    const float* vals = (const float*)d_in[4];
    const int*   row  = (const int*)d_in[5];
    const int*   col  = (const int*)d_in[6];
    float* out = (float*)d_out;

    const int smemBytes = 2 * 128 * XSTR * sizeof(uint32_t);   // 69632 B
    cudaFuncSetAttribute(gin_gemm_mma_kernel,
                         cudaFuncAttributeMaxDynamicSharedMemorySize, smemBytes);

    static cudaStream_t s2 = nullptr;
    static cudaEvent_t evFork = nullptr, evJoin = nullptr;
    if (s2 == nullptr) {
        cudaStreamCreateWithFlags(&s2, cudaStreamNonBlocking);
        cudaEventCreateWithFlags(&evFork, cudaEventDisableTiming);
        cudaEventCreateWithFlags(&evJoin, cudaEventDisableTiming);
    }

    // Fork: side stream runs the edge-bucket chain.
    cudaEventRecord(evFork, 0);
    cudaStreamWaitEvent(s2, evFork, 0);

    // side stream: zero cursors -> bucket build
    gin_zero_kernel<<<(N_NODES + 255) / 256, 256, 0, s2>>>();
    gin_build_kernel<<<(N_EDGES / 4 + 255) / 256, 256, 0, s2>>>(vals, row, col);

    // main stream: W convert -> fp16 HMMA GEMM
    gin_wsplit_kernel<<<(D * D / 2 + 255) / 256, 256>>>(W);
    gin_gemm_mma_kernel<<<(N_NODES + 127) / 128, 256, smemBytes>>>(x);

    // Join.
    cudaEventRecord(evJoin, s2);
    cudaStreamWaitEvent(0, evJoin, 0);

    const long long aggThreads = (long long)N_NODES * 32;
    gin_aggregate_kernel<<<(unsigned)((aggThreads + 255) / 256), 256>>>(bias, eps, out);
}